// round 10
// baseline (speedup 1.0000x reference)
#include <cuda_runtime.h>
#include <stdint.h>

// Problem constants (from reference setup_inputs)
#define BB 1024
#define RR 192
#define NMW 3          // 96 pair-offset bits per thread -> 3 words
#define NBLK (BB * 2)  // two blocks per batch (k-halves)

#define ALPHA 1.0f
#define BETA  1.0f
#define GAMMA 0.5f
#define DELTA 0.3f

// Scratch (no allocations allowed). Zero-initialized by CUDA runtime.
__device__ float    g_partials[NBLK * 4];
__device__ unsigned g_pairmask[RR * NMW];
__device__ unsigned g_count;   // self-resetting last-block ticket

// ---------------------------------------------------------------------------
// Pre-kernel: bake per-(thread t, offset k) adjacency bit.
// Flat: g = t*96 + kk, kk in [0,96), k = kk+1. 96 % 32 == 0 so every warp's
// 32 bits belong to one row -> ballot packs directly into g_pairmask[g>>5].
// ---------------------------------------------------------------------------
__global__ void fp_build_mask(const int* __restrict__ adj) {
    int g  = blockIdx.x * 1024 + threadIdx.x;
    int t  = g / 96;
    int kk = g % 96;
    int k  = kk + 1;
    int b2 = t + k; if (b2 >= RR) b2 -= RR;
    int i = t < b2 ? t : b2;
    int j = t < b2 ? b2 : t;
    int bit = (adj[i * RR + j] > 0) ? 1 : 0;
    unsigned bal = __ballot_sync(0xffffffffu, bit);
    if ((g & 31) == 0) g_pairmask[g >> 5] = bal;
}

// ---------------------------------------------------------------------------
// Main kernel: 2 blocks per batch. Block (b, half) handles offsets
// k in [1,48] (half=0) or [49,96] (half=1). Thread t owns room i=t in
// registers, streams room j = t+k from duplicated float2 smem (LDS.64,
// no wrap, conflict-free). MUFU rsqrt for distance; adjacency bit applied
// as a bitwise AND mask. MSE terms only in half=0. Last block (atomic
// ticket) performs the deterministic final reduction.
// ---------------------------------------------------------------------------
__global__ __launch_bounds__(RR, 8) void fp_main(
    const float2* __restrict__ pu, const float2* __restrict__ su,
    const float2* __restrict__ tp, const float2* __restrict__ ts,
    float* __restrict__ out)
{
    __shared__ float2 sxy[2 * RR];   // (x, y)
    __shared__ float2 swh[2 * RR];   // (x+w, y+h)
    __shared__ float2 sc [2 * RR];   // (cx, cy)
    __shared__ float  red[6][4];
    __shared__ int    is_last;

    const int t    = threadIdx.x;
    const int b    = blockIdx.x >> 1;
    const int half = blockIdx.x & 1;
    const int base = b * RR + t;

    float2 p = pu[base];
    float2 s = su[base];

    const float xi  = p.x, yi = p.y;
    const float xwi = p.x + s.x;
    const float yhi = p.y + s.y;
    const float cxi = fmaf(0.5f, s.x, p.x);
    const float cyi = fmaf(0.5f, s.y, p.y);

    float2 vxy = make_float2(xi,  yi);
    float2 vwh = make_float2(xwi, yhi);
    float2 vc  = make_float2(cxi, cyi);
    sxy[t] = vxy; sxy[t + RR] = vxy;
    swh[t] = vwh; swh[t + RR] = vwh;
    sc [t] = vc;  sc [t + RR] = vc;

    // MSE partials (only half=0 contributes, avoids double-count)
    float pos_acc = 0.0f, size_acc = 0.0f;
    if (half == 0) {
        float2 q = tp[base];
        float2 z = ts[base];
        float dpx = p.x - q.x, dpy = p.y - q.y;
        pos_acc = fmaf(dpx, dpx, dpy * dpy);
        float dsx = s.x - z.x, dsy = s.y - z.y;
        size_acc = fmaf(dsx, dsx, dsy * dsy);
    }

    // two mask words for this half
    const unsigned w0 = g_pairmask[t * NMW + half];        // m0 or m1
    const unsigned w1 = g_pairmask[t * NMW + half + 1];    // m1 or m2

    __syncthreads();

    float ovl = 0.0f, adjacc = 0.0f;

#define PAIR_STEP(JJ, SMASK) do {                                             \
        int jj = (JJ);                                                        \
        unsigned msk = (unsigned)(SMASK);                                     \
        float2 aj = sxy[jj];                                                  \
        float2 bj = swh[jj];                                                  \
        float2 cj = sc [jj];                                                  \
        float ow = fminf(xwi, bj.x) - fmaxf(xi, aj.x);                        \
        float oh = fminf(yhi, bj.y) - fmaxf(yi, aj.y);                        \
        ow = fmaxf(ow, 0.0f);                                                 \
        oh = fmaxf(oh, 0.0f);                                                 \
        ovl = fmaf(ow, oh, ovl);                                              \
        float dx = cxi - cj.x;                                                \
        float dy = cyi - cj.y;                                                \
        float sq = fmaf(dx, dx, dy * dy);                                     \
        sq = fmaxf(sq, 1e-30f);                                               \
        float r;                                                              \
        asm("rsqrt.approx.f32 %0, %1;" : "=f"(r) : "f"(sq));                  \
        r = __uint_as_float(__float_as_uint(r) & msk);                        \
        adjacc = fmaf(sq, r, adjacc);                                         \
    } while (0)

    // sign-extended mask (all-ones if bit kk of word set)
#define SMSK(word, kk) (((int)((word) << (31 - (kk)))) >> 31)

    if (half == 0) {
        // k = 1..32  (word w0 = m0), k = 33..48 (word w1 = m1 bits 0..15)
#pragma unroll
        for (int kk = 0; kk < 32; ++kk)
            PAIR_STEP(t + 1 + kk, SMSK(w0, kk));
#pragma unroll
        for (int kk = 0; kk < 16; ++kk)
            PAIR_STEP(t + 33 + kk, SMSK(w1, kk));
    } else {
        // k = 49..64 (word w0 = m1 bits 16..31), k = 65..95 (w1 = m2 bits 0..30)
#pragma unroll
        for (int kk = 16; kk < 32; ++kk)
            PAIR_STEP(t + 33 + kk, SMSK(w0, kk));
#pragma unroll
        for (int kk = 0; kk < 31; ++kk)
            PAIR_STEP(t + 65 + kk, SMSK(w1, kk));
        // k = 96: circular distance 96 pairs appear twice; only t<96 keeps one
        if (t < 96)
            PAIR_STEP(t + 96, ((int)w1) >> 31);
    }

#undef PAIR_STEP
#undef SMSK

    // -------- block reduction (deterministic, no atomics) --------
    const unsigned FULL = 0xffffffffu;
#pragma unroll
    for (int o = 16; o > 0; o >>= 1) {
        pos_acc  += __shfl_down_sync(FULL, pos_acc,  o);
        size_acc += __shfl_down_sync(FULL, size_acc, o);
        ovl      += __shfl_down_sync(FULL, ovl,      o);
        adjacc   += __shfl_down_sync(FULL, adjacc,   o);
    }
    int warp = t >> 5, lane = t & 31;
    if (lane == 0) {
        red[warp][0] = pos_acc;
        red[warp][1] = size_acc;
        red[warp][2] = ovl;
        red[warp][3] = adjacc;
    }
    __syncthreads();
    if (t == 0) {
        float s0 = 0.f, s1 = 0.f, s2 = 0.f, s3 = 0.f;
#pragma unroll
        for (int w = 0; w < 6; ++w) {
            s0 += red[w][0]; s1 += red[w][1];
            s2 += red[w][2]; s3 += red[w][3];
        }
        g_partials[blockIdx.x * 4 + 0] = s0;
        g_partials[blockIdx.x * 4 + 1] = s1;
        g_partials[blockIdx.x * 4 + 2] = s2;
        g_partials[blockIdx.x * 4 + 3] = s3;
        __threadfence();
        unsigned old = atomicAdd(&g_count, 1u);
        is_last = (old == (unsigned)(NBLK - 1)) ? 1 : 0;
    }
    __syncthreads();

    // -------- last block: deterministic final reduction + epilogue --------
    if (is_last) {
        float v0 = 0.f, v1 = 0.f, v2 = 0.f, v3 = 0.f;
        // fixed strided order: deterministic regardless of which block is last
        for (int i = t; i < NBLK; i += RR) {
            v0 += g_partials[i * 4 + 0];
            v1 += g_partials[i * 4 + 1];
            v2 += g_partials[i * 4 + 2];
            v3 += g_partials[i * 4 + 3];
        }
#pragma unroll
        for (int o = 16; o > 0; o >>= 1) {
            v0 += __shfl_down_sync(FULL, v0, o);
            v1 += __shfl_down_sync(FULL, v1, o);
            v2 += __shfl_down_sync(FULL, v2, o);
            v3 += __shfl_down_sync(FULL, v3, o);
        }
        __syncthreads();   // red[] reuse safe (prior reads complete)
        if (lane == 0) {
            red[warp][0] = v0; red[warp][1] = v1;
            red[warp][2] = v2; red[warp][3] = v3;
        }
        __syncthreads();
        if (t == 0) {
            float s0 = 0.f, s1 = 0.f, s2 = 0.f, s3 = 0.f;
#pragma unroll
            for (int w = 0; w < 6; ++w) {
                s0 += red[w][0]; s1 += red[w][1];
                s2 += red[w][2]; s3 += red[w][3];
            }
            float pos_loss  = s0 * (1.0f / (float)(BB * RR * 2));
            float size_loss = s1 * (1.0f / (float)(BB * RR * 2));
            float ovl_pen   = s2 * (1.0f / (float)BB);
            float adj_loss  = s3 * (1.0f / (float)BB);
            out[0] = ALPHA * pos_loss + BETA * size_loss
                   + GAMMA * ovl_pen + DELTA * adj_loss;
            out[1] = pos_loss;
            out[2] = size_loss;
            out[3] = ovl_pen;
            out[4] = adj_loss;
            g_count = 0;   // reset for next graph replay
        }
    }
}

// ---------------------------------------------------------------------------
// Harness entry point
// ---------------------------------------------------------------------------
extern "C" void kernel_launch(void* const* d_in, const int* in_sizes, int n_in,
                              void* d_out, int out_size) {
    (void)in_sizes; (void)n_in; (void)out_size;
    const float2* pu = (const float2*)d_in[0];
    const float2* su = (const float2*)d_in[1];
    const float2* tp = (const float2*)d_in[2];
    const float2* ts = (const float2*)d_in[3];
    const int*   adj = (const int*)d_in[4];
    float* out = (float*)d_out;

    fp_build_mask<<<18, 1024>>>(adj);
    fp_main<<<NBLK, RR>>>(pu, su, tp, ts, out);
}

// round 15
// speedup vs baseline: 1.0850x; 1.0850x over previous
#include <cuda_runtime.h>
#include <stdint.h>

// Problem constants (from reference setup_inputs)
#define BB 1024
#define RR 192
#define NMW 3          // 96 pair-offset bits per thread -> 3 words

#define ALPHA 1.0f
#define BETA  1.0f
#define GAMMA 0.5f
#define DELTA 0.3f

// Scratch (no allocations allowed). Zero-initialized by CUDA runtime.
__device__ float    g_partials[BB * 4];
__device__ unsigned g_pairmask[RR * NMW];
__device__ unsigned g_count;   // self-resetting last-block ticket

// ---------------------------------------------------------------------------
// Pre-kernel: bake per-(thread t, offset k) adjacency bit.
// Flat: g = t*96 + kk, kk in [0,96), k = kk+1. 96 % 32 == 0 so every warp's
// 32 bits belong to one row -> ballot packs directly into g_pairmask[g>>5].
// ---------------------------------------------------------------------------
__global__ void fp_build_mask(const int* __restrict__ adj) {
    int g  = blockIdx.x * 1024 + threadIdx.x;
    int t  = g / 96;
    int kk = g % 96;
    int k  = kk + 1;
    int b2 = t + k; if (b2 >= RR) b2 -= RR;
    int i = t < b2 ? t : b2;
    int j = t < b2 ? b2 : t;
    int bit = (adj[i * RR + j] > 0) ? 1 : 0;
    unsigned bal = __ballot_sync(0xffffffffu, bit);
    if ((g & 31) == 0) g_pairmask[g >> 5] = bal;
}

// ---------------------------------------------------------------------------
// Main kernel: one block per batch (R7 structure = lowest fixed cost).
// Thread t owns room i=t in registers; streams room j = t+k as a SINGLE
// LDS.128 of (x, y, w, h) from duplicated float4 smem (16B/pair instead of
// 24B -> smem crossbar 78% -> 52%), reconstructing xw/yh/cx/cy in the fma
// pipe. MUFU rsqrt for distance; adjacency bit applied as bitwise AND mask.
// Last block (atomic ticket) does the deterministic final reduction.
// ---------------------------------------------------------------------------
__global__ __launch_bounds__(RR, 6) void fp_main(
    const float2* __restrict__ pu, const float2* __restrict__ su,
    const float2* __restrict__ tp, const float2* __restrict__ ts,
    float* __restrict__ out)
{
    __shared__ float4 sr[2 * RR];    // (x, y, w, h) duplicated
    __shared__ float  red[6][4];
    __shared__ int    is_last;

    const int t = threadIdx.x;
    const int b = blockIdx.x;
    const int base = b * RR + t;

    float2 p = pu[base];
    float2 s = su[base];
    float2 q = tp[base];
    float2 z = ts[base];

    const float xi  = p.x, yi = p.y;
    const float xwi = p.x + s.x;
    const float yhi = p.y + s.y;
    const float cxi = fmaf(0.5f, s.x, p.x);
    const float cyi = fmaf(0.5f, s.y, p.y);

    float4 v = make_float4(p.x, p.y, s.x, s.y);
    sr[t] = v; sr[t + RR] = v;

    // MSE partials for this thread's room
    float dpx = p.x - q.x, dpy = p.y - q.y;
    float pos_acc = fmaf(dpx, dpx, dpy * dpy);
    float dsx = s.x - z.x, dsy = s.y - z.y;
    float size_acc = fmaf(dsx, dsx, dsy * dsy);

    const unsigned m0 = g_pairmask[t * NMW + 0];
    const unsigned m1 = g_pairmask[t * NMW + 1];
    const unsigned m2 = g_pairmask[t * NMW + 2];

    __syncthreads();

    float ovl = 0.0f, adjacc = 0.0f;

#define PAIR_STEP(JJ, SMASK) do {                                             \
        int jj = (JJ);                                                        \
        unsigned msk = (unsigned)(SMASK);                                     \
        float4 rj = sr[jj];                                                   \
        float xwj = rj.x + rj.z;                                              \
        float yhj = rj.y + rj.w;                                              \
        float cxj = fmaf(0.5f, rj.z, rj.x);                                   \
        float cyj = fmaf(0.5f, rj.w, rj.y);                                   \
        float ow = fminf(xwi, xwj) - fmaxf(xi, rj.x);                         \
        float oh = fminf(yhi, yhj) - fmaxf(yi, rj.y);                         \
        ow = fmaxf(ow, 0.0f);                                                 \
        oh = fmaxf(oh, 0.0f);                                                 \
        ovl = fmaf(ow, oh, ovl);                                              \
        float dx = cxi - cxj;                                                 \
        float dy = cyi - cyj;                                                 \
        float sq = fmaf(dx, dx, dy * dy);                                     \
        sq = fmaxf(sq, 1e-30f);                                               \
        float r;                                                              \
        asm("rsqrt.approx.f32 %0, %1;" : "=f"(r) : "f"(sq));                  \
        r = __uint_as_float(__float_as_uint(r) & msk);                        \
        adjacc = fmaf(sq, r, adjacc);                                         \
    } while (0)

    // sign-extended mask (all-ones if bit kk of word set)
#define SMSK(word, kk) (((int)((word) << (31 - (kk)))) >> 31)

    // k = 1..32  (mask word m0)
#pragma unroll
    for (int kk = 0; kk < 32; ++kk)
        PAIR_STEP(t + 1 + kk, SMSK(m0, kk));
    // k = 33..64 (mask word m1)
#pragma unroll
    for (int kk = 0; kk < 32; ++kk)
        PAIR_STEP(t + 33 + kk, SMSK(m1, kk));
    // k = 65..95 (mask word m2, bits 0..30)
#pragma unroll
    for (int kk = 0; kk < 31; ++kk)
        PAIR_STEP(t + 65 + kk, SMSK(m2, kk));
    // k = 96: circular distance 96 pairs appear twice; only t<96 keeps one
    if (t < 96)
        PAIR_STEP(t + 96, ((int)m2) >> 31);

#undef PAIR_STEP
#undef SMSK

    // -------- block reduction (deterministic, no atomics) --------
    const unsigned FULL = 0xffffffffu;
#pragma unroll
    for (int o = 16; o > 0; o >>= 1) {
        pos_acc  += __shfl_down_sync(FULL, pos_acc,  o);
        size_acc += __shfl_down_sync(FULL, size_acc, o);
        ovl      += __shfl_down_sync(FULL, ovl,      o);
        adjacc   += __shfl_down_sync(FULL, adjacc,   o);
    }
    int warp = t >> 5, lane = t & 31;
    if (lane == 0) {
        red[warp][0] = pos_acc;
        red[warp][1] = size_acc;
        red[warp][2] = ovl;
        red[warp][3] = adjacc;
    }
    __syncthreads();
    if (t == 0) {
        float s0 = 0.f, s1 = 0.f, s2 = 0.f, s3 = 0.f;
#pragma unroll
        for (int w = 0; w < 6; ++w) {
            s0 += red[w][0]; s1 += red[w][1];
            s2 += red[w][2]; s3 += red[w][3];
        }
        g_partials[b * 4 + 0] = s0;
        g_partials[b * 4 + 1] = s1;
        g_partials[b * 4 + 2] = s2;
        g_partials[b * 4 + 3] = s3;
        __threadfence();
        unsigned old = atomicAdd(&g_count, 1u);
        is_last = (old == (unsigned)(BB - 1)) ? 1 : 0;
    }
    __syncthreads();

    // -------- last block: deterministic final reduction + epilogue --------
    if (is_last) {
        float v0 = 0.f, v1 = 0.f, v2 = 0.f, v3 = 0.f;
        // fixed strided order: deterministic regardless of which block is last
        for (int i = t; i < BB; i += RR) {
            v0 += g_partials[i * 4 + 0];
            v1 += g_partials[i * 4 + 1];
            v2 += g_partials[i * 4 + 2];
            v3 += g_partials[i * 4 + 3];
        }
#pragma unroll
        for (int o = 16; o > 0; o >>= 1) {
            v0 += __shfl_down_sync(FULL, v0, o);
            v1 += __shfl_down_sync(FULL, v1, o);
            v2 += __shfl_down_sync(FULL, v2, o);
            v3 += __shfl_down_sync(FULL, v3, o);
        }
        __syncthreads();   // red[] reuse safe (prior reads complete)
        if (lane == 0) {
            red[warp][0] = v0; red[warp][1] = v1;
            red[warp][2] = v2; red[warp][3] = v3;
        }
        __syncthreads();
        if (t == 0) {
            float s0 = 0.f, s1 = 0.f, s2 = 0.f, s3 = 0.f;
#pragma unroll
            for (int w = 0; w < 6; ++w) {
                s0 += red[w][0]; s1 += red[w][1];
                s2 += red[w][2]; s3 += red[w][3];
            }
            float pos_loss  = s0 * (1.0f / (float)(BB * RR * 2));
            float size_loss = s1 * (1.0f / (float)(BB * RR * 2));
            float ovl_pen   = s2 * (1.0f / (float)BB);
            float adj_loss  = s3 * (1.0f / (float)BB);
            out[0] = ALPHA * pos_loss + BETA * size_loss
                   + GAMMA * ovl_pen + DELTA * adj_loss;
            out[1] = pos_loss;
            out[2] = size_loss;
            out[3] = ovl_pen;
            out[4] = adj_loss;
            g_count = 0;   // reset for next graph replay
        }
    }
}

// ---------------------------------------------------------------------------
// Harness entry point
// ---------------------------------------------------------------------------
extern "C" void kernel_launch(void* const* d_in, const int* in_sizes, int n_in,
                              void* d_out, int out_size) {
    (void)in_sizes; (void)n_in; (void)out_size;
    const float2* pu = (const float2*)d_in[0];
    const float2* su = (const float2*)d_in[1];
    const float2* tp = (const float2*)d_in[2];
    const float2* ts = (const float2*)d_in[3];
    const int*   adj = (const int*)d_in[4];
    float* out = (float*)d_out;

    fp_build_mask<<<18, 1024>>>(adj);
    fp_main<<<BB, RR>>>(pu, su, tp, ts, out);
}